// round 1
// baseline (speedup 1.0000x reference)
#include <cuda_runtime.h>
#include <cuda_bf16.h>
#include <cstdint>

// Embedding gather: out[token, d] = W[d * VOCAB + ids[token]]
// B=4, S=4096 -> 16384 tokens; D_MODEL=1024; VOCAB=50257.
// W is row-major [D_MODEL, VOCAB] (d-major), so a token's column is strided
// by VOCAB floats. Writes are fully coalesced float4; reads are 4 independent
// strided LDGs per thread for memory-level parallelism.

#define VOCAB   50257
#define D_MODEL 1024
#define N_TOK   (4 * 4096)

__global__ __launch_bounds__(256, 8)
void input_layer_gather_kernel(const int* __restrict__ ids,
                               const float* __restrict__ W,
                               float* __restrict__ out) {
    const int token = blockIdx.x;
    const int id = __ldg(&ids[token]);

    // Each thread handles 4 consecutive d values -> one float4 store.
    const int d0 = threadIdx.x * 4;

    const float* __restrict__ col = W + id;
    float4 v;
    v.x = __ldg(&col[(long)(d0 + 0) * VOCAB]);
    v.y = __ldg(&col[(long)(d0 + 1) * VOCAB]);
    v.z = __ldg(&col[(long)(d0 + 2) * VOCAB]);
    v.w = __ldg(&col[(long)(d0 + 3) * VOCAB]);

    *reinterpret_cast<float4*>(out + (long)token * D_MODEL + d0) = v;
}

extern "C" void kernel_launch(void* const* d_in, const int* in_sizes, int n_in,
                              void* d_out, int out_size) {
    // Identify inputs by size to be robust to ordering:
    // ids: 16384 int32, W: 1024*50257 float32.
    const int* ids = nullptr;
    const float* W = nullptr;
    for (int i = 0; i < n_in; i++) {
        if (in_sizes[i] == N_TOK) ids = (const int*)d_in[i];
        else if (in_sizes[i] == D_MODEL * VOCAB) W = (const float*)d_in[i];
    }
    float* out = (float*)d_out;

    dim3 grid(N_TOK);
    dim3 block(256);  // 256 threads * 4 d-values = 1024 = D_MODEL
    input_layer_gather_kernel<<<grid, block>>>(ids, W, out);
}

// round 2
// speedup vs baseline: 1.4252x; 1.4252x over previous
#include <cuda_runtime.h>
#include <cuda_bf16.h>
#include <cstdint>

// Embedding gather with counting-sort prepass for L2 locality.
// out[token, :] = W[:, ids[token]]  (W row-major [D_MODEL, VOCAB])
//
// Random token ids scatter reads across the whole 200 MB W -> L2 thrash,
// ~1.35 GB DRAM traffic measured in R1. Sorting tokens by id makes blocks
// with nearby ids run concurrently, so the strided-gather sector
// amplification is absorbed by L2 and DRAM reads collapse to the unique
// sector footprint (~191 MB).

#define VOCAB   50257
#define D_MODEL 1024
#define N_TOK   (4 * 4096)

// Scratch (device globals -- no allocation allowed in kernel_launch).
__device__ int g_hist[VOCAB];   // histogram
__device__ int g_off[VOCAB];    // exclusive prefix (mutated by scatter)
__device__ int g_sid[N_TOK];    // ids in sorted order
__device__ int g_ord[N_TOK];    // original token index per sorted slot

__global__ void zero_hist_kernel() {
    int i = blockIdx.x * blockDim.x + threadIdx.x;
    if (i < VOCAB) g_hist[i] = 0;
}

__global__ void hist_kernel(const int* __restrict__ ids) {
    int i = blockIdx.x * blockDim.x + threadIdx.x;
    if (i < N_TOK) atomicAdd(&g_hist[ids[i]], 1);
}

// Single-block chunked Hillis-Steele exclusive scan over VOCAB bins.
__global__ void scan_kernel() {
    __shared__ int s[1024];
    const int tid = threadIdx.x;
    int total = 0;
    for (int base = 0; base < VOCAB; base += 1024) {
        int idx = base + tid;
        int v = (idx < VOCAB) ? g_hist[idx] : 0;
        s[tid] = v;
        __syncthreads();
        #pragma unroll
        for (int off = 1; off < 1024; off <<= 1) {
            int t = (tid >= off) ? s[tid - off] : 0;
            __syncthreads();
            s[tid] += t;
            __syncthreads();
        }
        if (idx < VOCAB) g_off[idx] = total + s[tid] - v;  // exclusive
        int chunk_sum = s[1023];
        __syncthreads();
        total += chunk_sum;
    }
}

__global__ void scatter_kernel(const int* __restrict__ ids) {
    int i = blockIdx.x * blockDim.x + threadIdx.x;
    if (i < N_TOK) {
        int id = ids[i];
        int pos = atomicAdd(&g_off[id], 1);
        g_sid[pos] = id;
        g_ord[pos] = i;
    }
}

// Main gather: block b handles sorted slot b. Reads for nearby blocks hit
// nearby W columns -> L2 absorbs the strided-load sector amplification.
// Writes: one coalesced float4 row per original token.
__global__ __launch_bounds__(256, 8)
void gather_kernel(const float* __restrict__ W, float* __restrict__ out) {
    const int slot  = blockIdx.x;
    const int id    = g_sid[slot];
    const int token = g_ord[slot];

    const int d0 = threadIdx.x * 4;
    const float* __restrict__ col = W + id;
    float4 v;
    v.x = __ldg(&col[(long)(d0 + 0) * VOCAB]);
    v.y = __ldg(&col[(long)(d0 + 1) * VOCAB]);
    v.z = __ldg(&col[(long)(d0 + 2) * VOCAB]);
    v.w = __ldg(&col[(long)(d0 + 3) * VOCAB]);

    *reinterpret_cast<float4*>(out + (long)token * D_MODEL + d0) = v;
}

extern "C" void kernel_launch(void* const* d_in, const int* in_sizes, int n_in,
                              void* d_out, int out_size) {
    const int* ids = nullptr;
    const float* W = nullptr;
    for (int i = 0; i < n_in; i++) {
        if (in_sizes[i] == N_TOK) ids = (const int*)d_in[i];
        else if (in_sizes[i] == D_MODEL * VOCAB) W = (const float*)d_in[i];
    }
    float* out = (float*)d_out;

    zero_hist_kernel<<<(VOCAB + 1023) / 1024, 1024>>>();
    hist_kernel<<<(N_TOK + 1023) / 1024, 1024>>>(ids);
    scan_kernel<<<1, 1024>>>();
    scatter_kernel<<<(N_TOK + 1023) / 1024, 1024>>>(ids);
    gather_kernel<<<N_TOK, 256>>>(W, out);
}

// round 3
// speedup vs baseline: 1.6301x; 1.1437x over previous
#include <cuda_runtime.h>
#include <cuda_bf16.h>
#include <cstdint>

// Embedding gather, tile-transpose formulation.
//   out[token, :] = W[:, ids[token]],  W row-major [D_MODEL, VOCAB]
//
// R1/R2 lesson: per-token strided gather wastes 8x in 32B sectors (4B used
// per sector) -> >=512MB through L2 no matter how good locality is.
// Fix: counting-sort tokens by id (prep kernels), then one block per
// 64-column tile of W loads its tile COALESCED into smem and distributes
// columns to the tokens whose ids fall in the tile. W is read exactly once,
// fully coalesced: ~200MB + 64MB writes total.

#define VOCAB    50257
#define D_MODEL  1024
#define N_TOK    (4 * 4096)

#define TILE_C   64                      // columns per block tile
#define TILE_D   128                     // rows per smem chunk
#define PAD      (TILE_C + 1)            // 65: odd -> conflict-free column reads
#define N_TILES  ((VOCAB + TILE_C - 1) / TILE_C)   // 786

// Scratch (device globals -- no allocation allowed).
__device__ int g_hist[VOCAB];
__device__ int g_off[VOCAB];    // after scatter: #tokens with id' <= id
__device__ int g_sid[N_TOK];    // ids sorted
__device__ int g_ord[N_TOK];    // original token index per sorted slot

__global__ void zero_hist_kernel() {
    int i = blockIdx.x * blockDim.x + threadIdx.x;
    if (i < VOCAB) g_hist[i] = 0;
}

__global__ void hist_kernel(const int* __restrict__ ids) {
    int i = blockIdx.x * blockDim.x + threadIdx.x;
    if (i < N_TOK) atomicAdd(&g_hist[ids[i]], 1);
}

// Exclusive prefix over VOCAB bins: thread-sequential chunks + one
// 1024-wide Hillis-Steele over thread totals. ~20 syncs total.
__global__ void scan_kernel() {
    __shared__ int s[1024];
    const int B = (VOCAB + 1023) / 1024;   // 50 bins per thread
    const int t = threadIdx.x;
    const int base = t * B;

    int sum = 0;
    for (int i = 0; i < B; i++) {
        int idx = base + i;
        if (idx < VOCAB) sum += g_hist[idx];
    }
    s[t] = sum;
    __syncthreads();
    #pragma unroll
    for (int off = 1; off < 1024; off <<= 1) {
        int v = (t >= off) ? s[t - off] : 0;
        __syncthreads();
        s[t] += v;
        __syncthreads();
    }
    int run = s[t] - sum;   // exclusive prefix of this thread's chunk
    for (int i = 0; i < B; i++) {
        int idx = base + i;
        if (idx < VOCAB) {
            int h = g_hist[idx];
            g_off[idx] = run;       // exclusive prefix per bin
            run += h;
        }
    }
}

__global__ void scatter_kernel(const int* __restrict__ ids) {
    int i = blockIdx.x * blockDim.x + threadIdx.x;
    if (i < N_TOK) {
        int id = ids[i];
        int pos = atomicAdd(&g_off[id], 1);   // g_off[id] becomes inclusive end
        g_sid[pos] = id;
        g_ord[pos] = i;
    }
}

// Block b owns W columns [c0, c0+64). Loads W[d0:d0+128, c0:c0+64]
// coalesced to smem, then each warp streams tokens of this tile, reading
// the token's column from smem (bank-conflict-free) and writing coalesced
// 128B rows of out.
__global__ __launch_bounds__(256, 6)
void gather_tile_kernel(const float* __restrict__ W, float* __restrict__ out) {
    const int tile = blockIdx.x;
    const int c0 = tile * TILE_C;

    // Sorted-slot range for ids in [c0, c0+TILE_C)
    const int c_hi = min(c0 + TILE_C, VOCAB) - 1;
    const int slot_start = (c0 == 0) ? 0 : g_off[c0 - 1];
    const int slot_end   = g_off[c_hi];
    if (slot_start >= slot_end) return;   // no tokens in this tile (uniform exit)

    __shared__ float tile_s[TILE_D * PAD];

    const int tid  = threadIdx.x;
    const int lane = tid & 31;
    const int wid  = tid >> 5;            // 8 warps

    // Load-phase mapping: 4 rows per pass (256 threads / 64 cols)
    const int lc   = tid & (TILE_C - 1);  // 0..63
    const int lr   = tid >> 6;            // 0..3
    const int cg   = c0 + lc;
    const bool cvalid = (cg < VOCAB);

    for (int d0 = 0; d0 < D_MODEL; d0 += TILE_D) {
        // ---- load W[d0:d0+128, c0:c0+64] coalesced ----
        #pragma unroll
        for (int i = 0; i < TILE_D / 4; i++) {
            int row = lr + i * 4;
            tile_s[row * PAD + lc] =
                cvalid ? __ldg(&W[(long)(d0 + row) * VOCAB + cg]) : 0.0f;
        }
        __syncthreads();

        // ---- distribute to tokens ----
        for (int t = slot_start + wid; t < slot_end; t += 8) {
            const int col = g_sid[t] - c0;
            float* __restrict__ orow = out + (long)g_ord[t] * D_MODEL + d0;
            #pragma unroll
            for (int k = 0; k < 4; k++) {
                // bank stride 65 -> conflict-free across lanes
                orow[k * 32 + lane] = tile_s[(k * 32 + lane) * PAD + col];
            }
        }
        __syncthreads();
    }
}

extern "C" void kernel_launch(void* const* d_in, const int* in_sizes, int n_in,
                              void* d_out, int out_size) {
    const int* ids = nullptr;
    const float* W = nullptr;
    for (int i = 0; i < n_in; i++) {
        if (in_sizes[i] == N_TOK) ids = (const int*)d_in[i];
        else if (in_sizes[i] == D_MODEL * VOCAB) W = (const float*)d_in[i];
    }
    float* out = (float*)d_out;

    zero_hist_kernel<<<(VOCAB + 1023) / 1024, 1024>>>();
    hist_kernel<<<(N_TOK + 1023) / 1024, 1024>>>(ids);
    scan_kernel<<<1, 1024>>>();
    scatter_kernel<<<(N_TOK + 1023) / 1024, 1024>>>(ids);
    gather_tile_kernel<<<N_TILES, 256>>>(W, out);
}

// round 4
// speedup vs baseline: 2.2097x; 1.3556x over previous
#include <cuda_runtime.h>
#include <cuda_bf16.h>
#include <cstdint>

// Embedding gather: out[token, :] = W[:, ids[token]], W row-major [D_MODEL, VOCAB].
// R4: (a) single fused prep kernel with tile-granular (786-bin) counting sort,
//     (b) cp.async double-buffered tile gather (load of chunk c+1 overlaps
//         distribution of chunk c).

#define VOCAB    50257
#define D_MODEL  1024
#define N_TOK    (4 * 4096)

#define TILE_C   64
#define TILE_BITS 6
#define N_TILES  ((VOCAB + TILE_C - 1) / TILE_C)   // 786
#define TILE_D   64
#define N_CHUNK  (D_MODEL / TILE_D)                // 16
#define PAD      (TILE_C + 1)                      // 65
#define BUF_ELEMS (TILE_D * PAD)                   // 4160 floats per buffer

// Scratch (device globals; no allocation allowed).
__device__ int g_start[N_TILES + 1];   // exclusive prefix per tile (+ total)
__device__ int g_slots[N_TOK];         // (col_in_tile << 16) | token_index

// ---------------- fused prep: hist + scan + scatter, one block ----------------
__global__ __launch_bounds__(1024, 1)
void prep_kernel(const int* __restrict__ ids) {
    __shared__ int s_hist[1024];      // 786 used (padded for scan)
    __shared__ int s_off[N_TILES];    // running scatter cursors
    const int t = threadIdx.x;

    s_hist[t] = 0;
    __syncthreads();

    int my_id[N_TOK / 1024];          // 16 tokens per thread, coalesced
    #pragma unroll
    for (int i = 0; i < N_TOK / 1024; i++) {
        my_id[i] = ids[t + i * 1024];
        atomicAdd(&s_hist[my_id[i] >> TILE_BITS], 1);
    }
    __syncthreads();

    // In-place Hillis-Steele inclusive scan over 1024 entries.
    const int mine = s_hist[t];
    #pragma unroll
    for (int off = 1; off < 1024; off <<= 1) {
        int v = (t >= off) ? s_hist[t - off] : 0;
        __syncthreads();
        s_hist[t] += v;
        __syncthreads();
    }
    const int excl = s_hist[t] - mine;   // exclusive prefix
    if (t <= N_TILES) g_start[t] = excl; // g_start[786] == N_TOK
    if (t < N_TILES)  s_off[t]  = excl;
    __syncthreads();

    #pragma unroll
    for (int i = 0; i < N_TOK / 1024; i++) {
        const int id  = my_id[i];
        const int pos = atomicAdd(&s_off[id >> TILE_BITS], 1);
        g_slots[pos] = ((id & (TILE_C - 1)) << 16) | (t + i * 1024);
    }
}

// ---------------- cp.async helpers ----------------
__device__ __forceinline__ void cp_async4(uint32_t saddr, const void* gptr) {
    asm volatile("cp.async.ca.shared.global [%0], [%1], 4;\n"
                 :: "r"(saddr), "l"(gptr));
}
__device__ __forceinline__ void cp_commit() {
    asm volatile("cp.async.commit_group;\n");
}
template <int N>
__device__ __forceinline__ void cp_wait() {
    asm volatile("cp.async.wait_group %0;\n" :: "n"(N));
}

// ---------------- gather: one block per 64-column tile ----------------
__global__ __launch_bounds__(256, 6)
void gather_tile_kernel(const float* __restrict__ W, float* __restrict__ out) {
    const int tile = blockIdx.x;
    const int slot_start = g_start[tile];
    const int slot_end   = g_start[tile + 1];
    if (slot_start >= slot_end) return;

    __shared__ float buf[2][BUF_ELEMS];

    const int tid  = threadIdx.x;
    const int lane = tid & 31;
    const int wid  = tid >> 5;               // 8 warps
    const int lc   = tid & (TILE_C - 1);     // 0..63
    const int lr   = tid >> TILE_BITS;       // 0..3
    const int cg   = tile * TILE_C + lc;
    const bool cvalid = (cg < VOCAB);        // only last tile has invalid cols
    const float* __restrict__ col_base = W + cg;

    uint32_t sbase[2];
    sbase[0] = (uint32_t)__cvta_generic_to_shared(&buf[0][0]);
    sbase[1] = (uint32_t)__cvta_generic_to_shared(&buf[1][0]);

    // Prologue: issue chunk 0 loads.
    if (cvalid) {
        #pragma unroll
        for (int i = 0; i < TILE_D / 4; i++) {
            const int row = lr + i * 4;
            cp_async4(sbase[0] + (uint32_t)((row * PAD + lc) * 4),
                      col_base + (long)row * VOCAB);
        }
    }
    cp_commit();

    for (int c = 0; c < N_CHUNK; c++) {
        const int cur = c & 1;
        // Issue next chunk into the other buffer before consuming current.
        if (c + 1 < N_CHUNK) {
            if (cvalid) {
                #pragma unroll
                for (int i = 0; i < TILE_D / 4; i++) {
                    const int row = (c + 1) * TILE_D + lr + i * 4;
                    cp_async4(sbase[cur ^ 1] + (uint32_t)((row % TILE_D * 0 + (lr + i * 4)) * PAD * 4 + lc * 4),
                              col_base + (long)row * VOCAB);
                }
            }
            cp_commit();
            cp_wait<1>();   // current chunk complete, next still in flight
        } else {
            cp_wait<0>();
        }
        __syncthreads();

        // Distribute chunk c to this tile's tokens.
        const int d0 = c * TILE_D;
        for (int s = slot_start + wid; s < slot_end; s += 8) {
            const int pk    = g_slots[s];
            const int col   = pk >> 16;
            const int token = pk & 0xFFFF;
            float* __restrict__ orow = out + (long)token * D_MODEL + d0;
            #pragma unroll
            for (int k = 0; k < TILE_D / 32; k++) {
                orow[k * 32 + lane] = buf[cur][(k * 32 + lane) * PAD + col];
            }
        }
        __syncthreads();
    }
}

extern "C" void kernel_launch(void* const* d_in, const int* in_sizes, int n_in,
                              void* d_out, int out_size) {
    const int* ids = nullptr;
    const float* W = nullptr;
    for (int i = 0; i < n_in; i++) {
        if (in_sizes[i] == N_TOK) ids = (const int*)d_in[i];
        else if (in_sizes[i] == D_MODEL * VOCAB) W = (const float*)d_in[i];
    }
    float* out = (float*)d_out;

    prep_kernel<<<1, 1024>>>(ids);
    gather_tile_kernel<<<N_TILES, 256>>>(W, out);
}